// round 1
// baseline (speedup 1.0000x reference)
#include <cuda_runtime.h>
#include <math.h>

// ---------------- problem constants (fixed shapes) ----------------
#define T_TOK   8192          // B*N tokens
#define D_IN    1024
#define E_NUM   4
#define O_DIM   4096
#define SLOTS   (2*T_TOK)     // top-2 -> 16384 (token,expert) slots
#define M_PAD   16896         // 16384 + 4*128 padding, = 132*128
#define MTILES  132
#define NTILES  (O_DIM/128)   // 32

// ---------------- device scratch (no runtime allocation) ----------------
__device__ float g_h [(size_t)M_PAD * O_DIM];   // expert hidden, fp32
__device__ float g_eo[(size_t)M_PAD * O_DIM];   // expert out (gate-scaled), fp32
__device__ int   g_tok[M_PAD];                  // slot -> token (-1 = pad)
__device__ float g_gw [M_PAD];                  // slot -> renormalized gate weight
__device__ int   g_te [2*T_TOK];                // token -> top-2 expert ids
__device__ float g_tw [2*T_TOK];                // token -> top-2 weights
__device__ int   g_slot_of[2*T_TOK];            // token -> its 2 slots
__device__ int   g_cnt[E_NUM];
__device__ int   g_cur[E_NUM];
__device__ int   g_off[E_NUM+1];                // 128-aligned segment starts

// ---------------- init ----------------
__global__ void init_kernel() {
    if (threadIdx.x < E_NUM) g_cnt[threadIdx.x] = 0;
}

// ---------------- router: logits = x@Wg + bg, softmax -> top2 -> renorm ----
__global__ void __launch_bounds__(256)
router_kernel(const float* __restrict__ x,
              const float* __restrict__ Wg,
              const float* __restrict__ bg)
{
    const int warp = threadIdx.x >> 5;
    const int lane = threadIdx.x & 31;
    const int t = blockIdx.x * 8 + warp;
    const float* xr = x + (size_t)t * D_IN;

    float a0 = 0.f, a1 = 0.f, a2 = 0.f, a3 = 0.f;
    for (int d = lane; d < D_IN; d += 32) {
        float xv = xr[d];
        float4 w = ((const float4*)Wg)[d];   // Wg row-major [D,4] -> one float4 per d
        a0 = fmaf(xv, w.x, a0);
        a1 = fmaf(xv, w.y, a1);
        a2 = fmaf(xv, w.z, a2);
        a3 = fmaf(xv, w.w, a3);
    }
#pragma unroll
    for (int o = 16; o; o >>= 1) {
        a0 += __shfl_xor_sync(0xffffffffu, a0, o);
        a1 += __shfl_xor_sync(0xffffffffu, a1, o);
        a2 += __shfl_xor_sync(0xffffffffu, a2, o);
        a3 += __shfl_xor_sync(0xffffffffu, a3, o);
    }
    if (lane == 0) {
        float l[4] = { a0 + bg[0], a1 + bg[1], a2 + bg[2], a3 + bg[3] };
        int i0 = 0;
#pragma unroll
        for (int e = 1; e < 4; ++e) if (l[e] > l[i0]) i0 = e;
        int i1 = -1;
#pragma unroll
        for (int e = 0; e < 4; ++e) {
            if (e == i0) continue;
            if (i1 < 0 || l[e] > l[i1]) i1 = e;
        }
        // softmax over all E then renorm over top-2 == logistic of logit gap
        float r  = expf(l[i1] - l[i0]);
        float w0 = 1.f / (1.f + r);
        float w1 = r * w0;
        g_te[2*t]   = i0;  g_te[2*t+1] = i1;
        g_tw[2*t]   = w0;  g_tw[2*t+1] = w1;
        atomicAdd(&g_cnt[i0], 1);
        atomicAdd(&g_cnt[i1], 1);
    }
}

// ---------------- offsets: 128-aligned per-expert segments ----------------
__global__ void offsets_kernel()
{
    const int tid = threadIdx.x;
    if (tid == 0) {
        int off = 0;
#pragma unroll
        for (int e = 0; e < E_NUM; ++e) {
            g_off[e] = off;
            off += (g_cnt[e] + 127) & ~127;
            g_cur[e] = 0;
        }
        g_off[E_NUM] = off;
    }
    for (int s = tid; s < M_PAD; s += blockDim.x) g_tok[s] = -1;
}

// ---------------- scatter: token -> compact slots ----------------
__global__ void scatter_kernel()
{
    const int t = blockIdx.x * blockDim.x + threadIdx.x;
    if (t >= T_TOK) return;
#pragma unroll
    for (int k = 0; k < 2; ++k) {
        int e = g_te[2*t + k];
        int p = atomicAdd(&g_cur[e], 1);
        int s = g_off[e] + p;
        g_tok[s] = t;
        g_gw [s] = g_tw[2*t + k];
        g_slot_of[2*t + k] = s;
    }
}

// ---------------- SGEMM: 128x128x16 tile, 8x8 per thread ----------------
// FIRST=true : A = gathered x rows (K=1024), epilogue GELU(acc+b1) -> g_h
// FIRST=false: A = g_h rows       (K=4096), epilogue gw*(acc+b2)  -> g_eo
template<bool FIRST>
__global__ void __launch_bounds__(256)
gemm_kernel(const float* __restrict__ X, int K,
            const float* __restrict__ W,
            const float* __restrict__ bias)
{
    __shared__ __align__(16) float As[16][132];  // transposed, stride 132 (16B mult)
    __shared__ __align__(16) float Bs[16][128];
    __shared__ int s_tok[128];

    const int tid = threadIdx.x;
    const int n0 = blockIdx.x * 128;
    const int m0 = blockIdx.y * 128;

    // which expert owns this M tile (tiles never straddle segments)
    int e = 0;
#pragma unroll
    for (int i = 1; i < E_NUM; ++i) if (m0 >= g_off[i]) e = i;

    if (FIRST && tid < 128) s_tok[tid] = g_tok[m0 + tid];
    __syncthreads();

    const float* Wp = W + (size_t)e * K * O_DIM + n0;

    // A-load mapping: 2 float4 per thread (row am, k-groups akg, akg+1)
    const int am  = tid >> 1;
    const int akg = (tid & 1) * 2;
    const float* arow;
    if (FIRST) {
        int tk = s_tok[am];
        arow = (tk >= 0) ? (X + (size_t)tk * D_IN) : nullptr;
    } else {
        arow = g_h + (size_t)(m0 + am) * O_DIM;
    }
    // B-load mapping: 2 float4 per thread
    const int bk = tid >> 5;
    const int bn = (tid & 31) * 4;

    const int ty = tid >> 4;   // 0..15 -> rows ty*8..ty*8+7
    const int tx = tid & 15;   // 0..15 -> cols tx*8..tx*8+7

    float acc[8][8];
#pragma unroll
    for (int i = 0; i < 8; ++i)
#pragma unroll
        for (int j = 0; j < 8; ++j) acc[i][j] = 0.f;

    for (int k0 = 0; k0 < K; k0 += 16) {
        // stage loads
#pragma unroll
        for (int q = 0; q < 2; ++q) {
            int kg = akg + q;
            float4 v = make_float4(0.f, 0.f, 0.f, 0.f);
            if (!FIRST || arow) v = *(const float4*)(arow + k0 + kg * 4);
            As[kg*4+0][am] = v.x;
            As[kg*4+1][am] = v.y;
            As[kg*4+2][am] = v.z;
            As[kg*4+3][am] = v.w;
        }
#pragma unroll
        for (int q = 0; q < 2; ++q) {
            int kk = bk + q * 8;
            float4 v = *(const float4*)(Wp + (size_t)(k0 + kk) * O_DIM + bn);
            *(float4*)&Bs[kk][bn] = v;
        }
        __syncthreads();

#pragma unroll
        for (int kk = 0; kk < 16; ++kk) {
            float4 A0 = *(const float4*)&As[kk][ty*8];
            float4 A1 = *(const float4*)&As[kk][ty*8 + 4];
            float4 B0 = *(const float4*)&Bs[kk][tx*8];
            float4 B1 = *(const float4*)&Bs[kk][tx*8 + 4];
            float a[8] = {A0.x,A0.y,A0.z,A0.w,A1.x,A1.y,A1.z,A1.w};
            float b[8] = {B0.x,B0.y,B0.z,B0.w,B1.x,B1.y,B1.z,B1.w};
#pragma unroll
            for (int i = 0; i < 8; ++i)
#pragma unroll
                for (int j = 0; j < 8; ++j)
                    acc[i][j] = fmaf(a[i], b[j], acc[i][j]);
        }
        __syncthreads();
    }

    // epilogue
    const float* bp = bias + e * O_DIM + n0 + tx * 8;
    float bv[8];
#pragma unroll
    for (int j = 0; j < 8; ++j) bv[j] = bp[j];

    float* Cbase = FIRST ? g_h : g_eo;
#pragma unroll
    for (int i = 0; i < 8; ++i) {
        int r = m0 + ty * 8 + i;
        float gw = FIRST ? 1.f : g_gw[r];
        float o[8];
#pragma unroll
        for (int j = 0; j < 8; ++j) {
            float v = acc[i][j] + bv[j];
            if (FIRST) v = 0.5f * v * (1.f + erff(v * 0.70710678118654752f));
            else       v *= gw;
            o[j] = v;
        }
        float* cp = Cbase + (size_t)r * O_DIM + n0 + tx * 8;
        *(float4*)cp       = make_float4(o[0], o[1], o[2], o[3]);
        *(float4*)(cp + 4) = make_float4(o[4], o[5], o[6], o[7]);
    }
}

// ---------------- combine two expert outputs + LayerNorm ----------------
__global__ void __launch_bounds__(256)
combine_ln_kernel(const float* __restrict__ ln_w,
                  const float* __restrict__ ln_b,
                  const float* __restrict__ gate_scale,
                  float* __restrict__ out)
{
    __shared__ __align__(16) float buf[O_DIM];
    __shared__ float s_red[32];
    __shared__ float s_mean, s_rstd;

    const int t   = blockIdx.x;
    const int tid = threadIdx.x;
    const int sA = g_slot_of[2*t];
    const int sB = g_slot_of[2*t + 1];
    const float4* ea = (const float4*)(g_eo + (size_t)sA * O_DIM);
    const float4* eb = (const float4*)(g_eo + (size_t)sB * O_DIM);
    const float gs = gate_scale[0];

    float sum = 0.f;
    for (int i = tid; i < O_DIM/4; i += 256) {
        float4 a = ea[i], b = eb[i];
        float4 v;
        v.x = gs * (a.x + b.x);
        v.y = gs * (a.y + b.y);
        v.z = gs * (a.z + b.z);
        v.w = gs * (a.w + b.w);
        ((float4*)buf)[i] = v;
        sum += v.x + v.y + v.z + v.w;
    }
#pragma unroll
    for (int o = 16; o; o >>= 1) sum += __shfl_xor_sync(0xffffffffu, sum, o);
    if ((tid & 31) == 0) s_red[tid >> 5] = sum;
    __syncthreads();
    if (tid < 32) {
        float v = (tid < 8) ? s_red[tid] : 0.f;
#pragma unroll
        for (int o = 4; o; o >>= 1) v += __shfl_xor_sync(0xffffffffu, v, o);
        if (tid == 0) s_mean = v * (1.f / O_DIM);
    }
    __syncthreads();
    const float mu = s_mean;

    float ssq = 0.f;
    for (int i = tid; i < O_DIM; i += 256) {
        float d = buf[i] - mu;
        ssq += d * d;
    }
#pragma unroll
    for (int o = 16; o; o >>= 1) ssq += __shfl_xor_sync(0xffffffffu, ssq, o);
    __syncthreads();                 // protect s_red reuse
    if ((tid & 31) == 0) s_red[tid >> 5] = ssq;
    __syncthreads();
    if (tid < 32) {
        float v = (tid < 8) ? s_red[tid] : 0.f;
#pragma unroll
        for (int o = 4; o; o >>= 1) v += __shfl_xor_sync(0xffffffffu, v, o);
        if (tid == 0) s_rstd = rsqrtf(v * (1.f / O_DIM) + 1e-5f);
    }
    __syncthreads();
    const float rstd = s_rstd;

    float4* op = (float4*)(out + (size_t)t * O_DIM);
    const float4* lw = (const float4*)ln_w;
    const float4* lb = (const float4*)ln_b;
    for (int i = tid; i < O_DIM/4; i += 256) {
        float4 v = ((float4*)buf)[i];
        float4 w = lw[i], b = lb[i];
        float4 r;
        r.x = (v.x - mu) * rstd * w.x + b.x;
        r.y = (v.y - mu) * rstd * w.y + b.y;
        r.z = (v.z - mu) * rstd * w.z + b.z;
        r.w = (v.w - mu) * rstd * w.w + b.w;
        op[i] = r;
    }
}

// ---------------- launch ----------------
extern "C" void kernel_launch(void* const* d_in, const int* in_sizes, int n_in,
                              void* d_out, int out_size)
{
    (void)in_sizes; (void)n_in; (void)out_size;
    const float* x  = (const float*)d_in[0];
    const float* Wg = (const float*)d_in[1];
    const float* bg = (const float*)d_in[2];
    const float* W1 = (const float*)d_in[3];
    const float* b1 = (const float*)d_in[4];
    const float* W2 = (const float*)d_in[5];
    const float* b2 = (const float*)d_in[6];
    const float* lw = (const float*)d_in[7];
    const float* lb = (const float*)d_in[8];
    const float* gs = (const float*)d_in[9];
    float* out = (float*)d_out;

    init_kernel<<<1, 32>>>();
    router_kernel<<<T_TOK / 8, 256>>>(x, Wg, bg);
    offsets_kernel<<<1, 256>>>();
    scatter_kernel<<<T_TOK / 256, 256>>>();

    // x = n-tile fast so a wave covers all N strips for few M strips:
    // keeps W[e] (<=67MB) L2-resident -> each operand streams from DRAM ~once.
    gemm_kernel<true ><<<dim3(NTILES, MTILES), 256>>>(x,       D_IN,  W1, b1);
    gemm_kernel<false><<<dim3(NTILES, MTILES), 256>>>(nullptr, O_DIM, W2, b2);

    combine_ln_kernel<<<T_TOK, 256>>>(lw, lb, gs, out);
}

// round 4
// speedup vs baseline: 2.9437x; 2.9437x over previous
#include <cuda_runtime.h>
#include <math.h>
#include <stdint.h>

// ---------------- problem constants ----------------
#define T_TOK   8192
#define D_IN    1024
#define E_NUM   4
#define O_DIM   4096
#define M_PAD   16896          // 132*128
#define MT      132
#define BM      128
#define BN      128
#define BK      32
#define NSTAGE  4
#define NT      (O_DIM/BN)     // 32

#define SMEM_STRIDE 36                       // floats per smem row (32 + 4 pad)
#define AB_BYTES   (128*SMEM_STRIDE*4)       // 18432 per operand per stage
#define STAGE_BYTES (2*AB_BYTES)             // 36864
#define SMEM_TOTAL  (NSTAGE*STAGE_BYTES)     // 147456

// ---------------- device scratch (referenced ONLY from device code) ----------
__device__ float g_xs [(size_t)M_PAD * D_IN];          // gathered+tf32 x
__device__ float g_w1t[(size_t)E_NUM * O_DIM * D_IN];  // W1^T tf32  [E][O][D]
__device__ float g_w2t[(size_t)E_NUM * O_DIM * O_DIM]; // W2^T tf32  [E][O][O]
__device__ float g_h  [(size_t)M_PAD * O_DIM];         // GELU out, tf32
__device__ float g_eo [(size_t)M_PAD * O_DIM];         // expert out * gate
__device__ int   g_tok[M_PAD];
__device__ float g_gw [M_PAD];
__device__ int   g_te [2*T_TOK];
__device__ float g_tw [2*T_TOK];
__device__ int   g_slot_of[2*T_TOK];
__device__ int   g_cnt[E_NUM];
__device__ int   g_cur[E_NUM];
__device__ int   g_off[E_NUM+1];

// ---------------- helpers ----------------
__device__ __forceinline__ float to_tf32(float v) {
    float r; asm("cvt.rna.tf32.f32 %0, %1;" : "=f"(r) : "f"(v)); return r;
}
__device__ __forceinline__ uint32_t smem_u32(const void* p) {
    uint32_t a;
    asm("{ .reg .u64 t; cvta.to.shared.u64 t, %1; cvt.u32.u64 %0, t; }" : "=r"(a) : "l"(p));
    return a;
}
#define CP_ASYNC16(dst_u32, src_ptr) \
    asm volatile("cp.async.cg.shared.global [%0], [%1], 16;" :: "r"(dst_u32), "l"(src_ptr))
#define CP_COMMIT() asm volatile("cp.async.commit_group;" ::: "memory")
#define CP_WAIT2()  asm volatile("cp.async.wait_group 2;" ::: "memory")

// m16n8k8 tf32 MMA, D = A*B + D  (row.col, f32 accum)
__device__ __forceinline__ void mma16n8k8(float* c, const uint32_t* a, const uint32_t* b) {
    asm volatile(
        "mma.sync.aligned.m16n8k8.row.col.f32.tf32.tf32.f32 "
        "{%0,%1,%2,%3}, {%4,%5,%6,%7}, {%8,%9}, {%0,%1,%2,%3};"
        : "+f"(c[0]), "+f"(c[1]), "+f"(c[2]), "+f"(c[3])
        : "r"(a[0]), "r"(a[1]), "r"(a[2]), "r"(a[3]), "r"(b[0]), "r"(b[1]));
}

// ---------------- small kernels ----------------
__global__ void init_kernel() { if (threadIdx.x < E_NUM) g_cnt[threadIdx.x] = 0; }

__global__ void __launch_bounds__(256)
router_kernel(const float* __restrict__ x, const float* __restrict__ Wg,
              const float* __restrict__ bg)
{
    const int warp = threadIdx.x >> 5, lane = threadIdx.x & 31;
    const int t = blockIdx.x * 8 + warp;
    const float* xr = x + (size_t)t * D_IN;
    float a0=0,a1=0,a2=0,a3=0;
    for (int d = lane; d < D_IN; d += 32) {
        float xv = xr[d];
        float4 w = ((const float4*)Wg)[d];
        a0 = fmaf(xv,w.x,a0); a1 = fmaf(xv,w.y,a1);
        a2 = fmaf(xv,w.z,a2); a3 = fmaf(xv,w.w,a3);
    }
#pragma unroll
    for (int o = 16; o; o >>= 1) {
        a0 += __shfl_xor_sync(~0u,a0,o); a1 += __shfl_xor_sync(~0u,a1,o);
        a2 += __shfl_xor_sync(~0u,a2,o); a3 += __shfl_xor_sync(~0u,a3,o);
    }
    if (lane == 0) {
        float l[4] = { a0+bg[0], a1+bg[1], a2+bg[2], a3+bg[3] };
        int i0 = 0;
#pragma unroll
        for (int e = 1; e < 4; ++e) if (l[e] > l[i0]) i0 = e;
        int i1 = -1;
#pragma unroll
        for (int e = 0; e < 4; ++e) { if (e==i0) continue; if (i1<0 || l[e]>l[i1]) i1 = e; }
        float r = expf(l[i1]-l[i0]);
        float w0 = 1.f/(1.f+r), w1 = r*w0;
        g_te[2*t]=i0; g_te[2*t+1]=i1; g_tw[2*t]=w0; g_tw[2*t+1]=w1;
        atomicAdd(&g_cnt[i0],1); atomicAdd(&g_cnt[i1],1);
    }
}

__global__ void offsets_kernel() {
    const int tid = threadIdx.x;
    if (tid == 0) {
        int off = 0;
#pragma unroll
        for (int e = 0; e < E_NUM; ++e) {
            g_off[e] = off; off += (g_cnt[e]+127)&~127; g_cur[e] = 0;
        }
        g_off[E_NUM] = off;
    }
    for (int s = tid; s < M_PAD; s += blockDim.x) g_tok[s] = -1;
}

__global__ void scatter_kernel() {
    const int t = blockIdx.x * blockDim.x + threadIdx.x;
    if (t >= T_TOK) return;
#pragma unroll
    for (int k = 0; k < 2; ++k) {
        int e = g_te[2*t+k];
        int p = atomicAdd(&g_cur[e],1);
        int s = g_off[e] + p;
        g_tok[s] = t; g_gw[s] = g_tw[2*t+k]; g_slot_of[2*t+k] = s;
    }
}

// gather x rows into slot order, convert to tf32 (pad rows -> 0)
__global__ void __launch_bounds__(256)
gather_convert_kernel(const float* __restrict__ x)
{
    const int s = blockIdx.x;
    const int tok = g_tok[s];
    float4* dst = (float4*)(g_xs + (size_t)s * D_IN);
    if (tok < 0) { dst[threadIdx.x] = make_float4(0,0,0,0); return; }
    float4 v = ((const float4*)(x + (size_t)tok * D_IN))[threadIdx.x];
    v.x = to_tf32(v.x); v.y = to_tf32(v.y); v.z = to_tf32(v.z); v.w = to_tf32(v.w);
    dst[threadIdx.x] = v;
}

// [R][C] -> [C][R] per expert (z), tf32 convert.
// WHICH selects the device-global destination INSIDE device code (no UB).
template<int WHICH>
__global__ void __launch_bounds__(256)
transpose_convert_kernel(const float* __restrict__ src, int R, int C)
{
    float* __restrict__ dst = (WHICH == 1) ? g_w1t : g_w2t;
    __shared__ float tile[32][33];
    const size_t so = (size_t)blockIdx.z * R * C;
    const int c0 = blockIdx.x*32, r0 = blockIdx.y*32;
    const int tx = threadIdx.x, ty = threadIdx.y;
#pragma unroll
    for (int i = 0; i < 32; i += 8)
        tile[ty+i][tx] = src[so + (size_t)(r0+ty+i)*C + c0+tx];
    __syncthreads();
#pragma unroll
    for (int i = 0; i < 32; i += 8)
        dst[so + (size_t)(c0+ty+i)*R + r0+tx] = to_tf32(tile[tx][ty+i]);
}

// ---------------- tf32 mma.sync GEMM: 128x128x32 CTA tile ----------------
// 8 warps (2m x 4n), warp tile 64x32 = 4x4 m16n8k8 fragments, 4-stage cp.async.
// All device-global operands resolved inside the kernel.
// FIRST=true : A=g_xs (K=1024),  B=g_w1t, epi GELU -> g_h (tf32)
// FIRST=false: A=g_h  (K=4096),  B=g_w2t, epi (acc+b)*gw -> g_eo
template<bool FIRST>
__global__ void __launch_bounds__(256, 1)
gemm_mma(const float* __restrict__ bias)
{
    constexpr int K  = FIRST ? D_IN : O_DIM;
    constexpr int KT = K / BK;
    const float* __restrict__ A  = FIRST ? g_xs  : g_h;
    const float* __restrict__ Bt = FIRST ? g_w1t : g_w2t;
    float* __restrict__ Cb       = FIRST ? g_h   : g_eo;

    extern __shared__ __align__(16) char smem[];
    const uint32_t sb = smem_u32(smem);
    const int tid  = threadIdx.x;
    const int wid  = tid >> 5, lane = tid & 31;
    const int wm   = wid >> 2;           // 0..1
    const int wn   = wid & 3;            // 0..3
    const int lq   = lane >> 2;          // 0..7 (group id)
    const int lr   = lane & 3;           // 0..3 (thread in group)
    const int n0 = blockIdx.x * BN;
    const int m0 = blockIdx.y * BM;

    int e = 0;
#pragma unroll
    for (int i = 1; i < E_NUM; ++i) if (m0 >= g_off[i]) e = i;

    const float* Ab = A  + (size_t)m0 * K;
    const float* Bb = Bt + (size_t)e * O_DIM * K + (size_t)n0 * K;

    // cp.async stage loader: A rows 0..127, B rows 0..127, 32 floats each
    auto load_stage = [&](int slot, int kblk) {
        const uint32_t sa = sb + slot * STAGE_BYTES;
        const uint32_t sB = sa + AB_BYTES;
        const int k0 = kblk * BK;
#pragma unroll
        for (int q = 0; q < 4; ++q) {
            int f = tid + 256*q;
            int row = f >> 3, kq = f & 7;
            CP_ASYNC16(sa + row*(SMEM_STRIDE*4) + kq*16, Ab + (size_t)row*K + k0 + kq*4);
            CP_ASYNC16(sB + row*(SMEM_STRIDE*4) + kq*16, Bb + (size_t)row*K + k0 + kq*4);
        }
    };

#pragma unroll
    for (int p = 0; p < 3; ++p) {
        if (p < KT) load_stage(p, p);
        CP_COMMIT();
    }

    float c[4][4][4];
#pragma unroll
    for (int mt = 0; mt < 4; ++mt)
#pragma unroll
        for (int nt = 0; nt < 4; ++nt)
#pragma unroll
            for (int i = 0; i < 4; ++i) c[mt][nt][i] = 0.f;

    for (int it = 0; it < KT; ++it) {
        CP_WAIT2();
        __syncthreads();
        if (it + 3 < KT) load_stage((it + 3) & (NSTAGE-1), it + 3);
        CP_COMMIT();

        const float* As = (const float*)(smem + (it & (NSTAGE-1)) * STAGE_BYTES);
        const float* Bs = As + AB_BYTES/4;

#pragma unroll
        for (int ks = 0; ks < 4; ++ks) {
            const int kb = ks * 8;
            uint32_t a[4][4];
#pragma unroll
            for (int mt = 0; mt < 4; ++mt) {
                const int r = wm*64 + mt*16 + lq;
                a[mt][0] = __float_as_uint(As[ r    *SMEM_STRIDE + kb + lr    ]);
                a[mt][1] = __float_as_uint(As[(r+8) *SMEM_STRIDE + kb + lr    ]);
                a[mt][2] = __float_as_uint(As[ r    *SMEM_STRIDE + kb + lr + 4]);
                a[mt][3] = __float_as_uint(As[(r+8) *SMEM_STRIDE + kb + lr + 4]);
            }
            uint32_t b[4][2];
#pragma unroll
            for (int nt = 0; nt < 4; ++nt) {
                const int ncol = wn*32 + nt*8 + lq;
                b[nt][0] = __float_as_uint(Bs[ncol*SMEM_STRIDE + kb + lr    ]);
                b[nt][1] = __float_as_uint(Bs[ncol*SMEM_STRIDE + kb + lr + 4]);
            }
#pragma unroll
            for (int mt = 0; mt < 4; ++mt)
#pragma unroll
                for (int nt = 0; nt < 4; ++nt)
                    mma16n8k8(c[mt][nt], a[mt], b[nt]);
        }
    }

    // ---------------- epilogue ----------------
#pragma unroll
    for (int mt = 0; mt < 4; ++mt) {
        const int r0 = m0 + wm*64 + mt*16 + lq;
        const int r1 = r0 + 8;
        const float gw0 = FIRST ? 1.f : g_gw[r0];
        const float gw1 = FIRST ? 1.f : g_gw[r1];
#pragma unroll
        for (int nt = 0; nt < 4; ++nt) {
            const int col = n0 + wn*32 + nt*8 + 2*lr;
            const float b0 = bias[e*O_DIM + col];
            const float b1 = bias[e*O_DIM + col + 1];
            float v00 = c[mt][nt][0] + b0, v01 = c[mt][nt][1] + b1;
            float v10 = c[mt][nt][2] + b0, v11 = c[mt][nt][3] + b1;
            if (FIRST) {
                v00 = to_tf32(0.5f*v00*(1.f+erff(v00*0.70710678118654752f)));
                v01 = to_tf32(0.5f*v01*(1.f+erff(v01*0.70710678118654752f)));
                v10 = to_tf32(0.5f*v10*(1.f+erff(v10*0.70710678118654752f)));
                v11 = to_tf32(0.5f*v11*(1.f+erff(v11*0.70710678118654752f)));
            } else {
                v00 *= gw0; v01 *= gw0; v10 *= gw1; v11 *= gw1;
            }
            *(float2*)(Cb + (size_t)r0*O_DIM + col) = make_float2(v00, v01);
            *(float2*)(Cb + (size_t)r1*O_DIM + col) = make_float2(v10, v11);
        }
    }
}

// ---------------- combine two expert outputs + LayerNorm ----------------
__global__ void __launch_bounds__(256)
combine_ln_kernel(const float* __restrict__ ln_w, const float* __restrict__ ln_b,
                  const float* __restrict__ gate_scale, float* __restrict__ out)
{
    __shared__ __align__(16) float buf[O_DIM];
    __shared__ float s_red[32];
    __shared__ float s_mean, s_rstd;

    const int t = blockIdx.x, tid = threadIdx.x;
    const int sA = g_slot_of[2*t], sB = g_slot_of[2*t+1];
    const float4* ea = (const float4*)(g_eo + (size_t)sA * O_DIM);
    const float4* eb = (const float4*)(g_eo + (size_t)sB * O_DIM);
    const float gs = gate_scale[0];

    float sum = 0.f;
    for (int i = tid; i < O_DIM/4; i += 256) {
        float4 a = ea[i], b = eb[i];
        float4 v = make_float4(gs*(a.x+b.x), gs*(a.y+b.y), gs*(a.z+b.z), gs*(a.w+b.w));
        ((float4*)buf)[i] = v;
        sum += v.x + v.y + v.z + v.w;
    }
#pragma unroll
    for (int o = 16; o; o >>= 1) sum += __shfl_xor_sync(~0u, sum, o);
    if ((tid & 31) == 0) s_red[tid >> 5] = sum;
    __syncthreads();
    if (tid < 32) {
        float v = (tid < 8) ? s_red[tid] : 0.f;
#pragma unroll
        for (int o = 4; o; o >>= 1) v += __shfl_xor_sync(~0u, v, o);
        if (tid == 0) s_mean = v * (1.f / O_DIM);
    }
    __syncthreads();
    const float mu = s_mean;

    float ssq = 0.f;
    for (int i = tid; i < O_DIM; i += 256) { float d = buf[i]-mu; ssq += d*d; }
#pragma unroll
    for (int o = 16; o; o >>= 1) ssq += __shfl_xor_sync(~0u, ssq, o);
    __syncthreads();
    if ((tid & 31) == 0) s_red[tid >> 5] = ssq;
    __syncthreads();
    if (tid < 32) {
        float v = (tid < 8) ? s_red[tid] : 0.f;
#pragma unroll
        for (int o = 4; o; o >>= 1) v += __shfl_xor_sync(~0u, v, o);
        if (tid == 0) s_rstd = rsqrtf(v * (1.f / O_DIM) + 1e-5f);
    }
    __syncthreads();
    const float rstd = s_rstd;

    float4* op = (float4*)(out + (size_t)t * O_DIM);
    const float4* lw = (const float4*)ln_w;
    const float4* lb = (const float4*)ln_b;
    for (int i = tid; i < O_DIM/4; i += 256) {
        float4 v = ((float4*)buf)[i], w = lw[i], b = lb[i];
        op[i] = make_float4((v.x-mu)*rstd*w.x+b.x, (v.y-mu)*rstd*w.y+b.y,
                            (v.z-mu)*rstd*w.z+b.z, (v.w-mu)*rstd*w.w+b.w);
    }
}

// ---------------- launch ----------------
extern "C" void kernel_launch(void* const* d_in, const int* in_sizes, int n_in,
                              void* d_out, int out_size)
{
    (void)in_sizes; (void)n_in; (void)out_size;
    const float* x  = (const float*)d_in[0];
    const float* Wg = (const float*)d_in[1];
    const float* bg = (const float*)d_in[2];
    const float* W1 = (const float*)d_in[3];
    const float* b1 = (const float*)d_in[4];
    const float* W2 = (const float*)d_in[5];
    const float* b2 = (const float*)d_in[6];
    const float* lw = (const float*)d_in[7];
    const float* lb = (const float*)d_in[8];
    const float* gs = (const float*)d_in[9];
    float* out = (float*)d_out;

    cudaFuncSetAttribute(gemm_mma<true>,  cudaFuncAttributeMaxDynamicSharedMemorySize, SMEM_TOTAL);
    cudaFuncSetAttribute(gemm_mma<false>, cudaFuncAttributeMaxDynamicSharedMemorySize, SMEM_TOTAL);

    init_kernel<<<1, 32>>>();
    router_kernel<<<T_TOK/8, 256>>>(x, Wg, bg);
    offsets_kernel<<<1, 256>>>();
    scatter_kernel<<<T_TOK/256, 256>>>();
    gather_convert_kernel<<<M_PAD, 256>>>(x);
    transpose_convert_kernel<1><<<dim3(O_DIM/32, D_IN/32, E_NUM), dim3(32,8)>>>(W1, D_IN, O_DIM);
    transpose_convert_kernel<2><<<dim3(O_DIM/32, O_DIM/32, E_NUM), dim3(32,8)>>>(W2, O_DIM, O_DIM);

    gemm_mma<true ><<<dim3(NT, MT), 256, SMEM_TOTAL>>>(b1);
    gemm_mma<false><<<dim3(NT, MT), 256, SMEM_TOTAL>>>(b2);

    combine_ln_kernel<<<T_TOK, 256>>>(lw, lb, gs, out);
}

// round 5
// speedup vs baseline: 6.4286x; 2.1838x over previous
#include <cuda_runtime.h>
#include <cuda_fp16.h>
#include <math.h>
#include <stdint.h>

// ---------------- problem constants ----------------
#define T_TOK   8192
#define D_IN    1024
#define E_NUM   4
#define O_DIM   4096
#define M_PAD   16896          // 132*128
#define MT      132
#define BM      128
#define BN      128
#define BK      32
#define NSTAGE  4
#define NT      (O_DIM/BN)     // 32

#define ROW_H    40                           // halfs per smem row (32 + 8 pad) = 80B
#define AB_BYTES (128*ROW_H*2)                // 10240 B per operand per stage
#define STAGE_BYTES (2*AB_BYTES)              // 20480 B
#define SMEM_TOTAL  (NSTAGE*STAGE_BYTES)      // 81920 B

// ---------------- device scratch (referenced ONLY from device code) ----------
__device__ __half g_xs [(size_t)M_PAD * D_IN];          // gathered fp16 x
__device__ __half g_w1t[(size_t)E_NUM * O_DIM * D_IN];  // W1^T fp16 [E][O][D]
__device__ __half g_w2t[(size_t)E_NUM * O_DIM * O_DIM]; // W2^T fp16 [E][O][O]
__device__ __half g_h  [(size_t)M_PAD * O_DIM];         // GELU out fp16
__device__ float  g_eo [(size_t)M_PAD * O_DIM];         // expert out * gate (fp32)
__device__ int    g_tok[M_PAD];
__device__ float  g_gw [M_PAD];
__device__ int    g_te [2*T_TOK];
__device__ float  g_tw [2*T_TOK];
__device__ int    g_slot_of[2*T_TOK];
__device__ int    g_cnt[E_NUM];
__device__ int    g_cur[E_NUM];
__device__ int    g_off[E_NUM+1];

// ---------------- helpers ----------------
__device__ __forceinline__ uint32_t smem_u32(const void* p) {
    uint32_t a;
    asm("{ .reg .u64 t; cvta.to.shared.u64 t, %1; cvt.u32.u64 %0, t; }" : "=r"(a) : "l"(p));
    return a;
}
#define CP_ASYNC16(dst_u32, src_ptr) \
    asm volatile("cp.async.cg.shared.global [%0], [%1], 16;" :: "r"(dst_u32), "l"(src_ptr))
#define CP_COMMIT() asm volatile("cp.async.commit_group;" ::: "memory")
#define CP_WAIT2()  asm volatile("cp.async.wait_group 2;" ::: "memory")

#define LDSM_X4(r0,r1,r2,r3,addr) \
    asm volatile("ldmatrix.sync.aligned.m8n8.x4.shared.b16 {%0,%1,%2,%3}, [%4];" \
        : "=r"(r0), "=r"(r1), "=r"(r2), "=r"(r3) : "r"(addr))

// m16n8k16 fp16 MMA, fp32 accum
__device__ __forceinline__ void mma16n8k16(float* c, const uint32_t* a, const uint32_t* b) {
    asm volatile(
        "mma.sync.aligned.m16n8k16.row.col.f32.f16.f16.f32 "
        "{%0,%1,%2,%3}, {%4,%5,%6,%7}, {%8,%9}, {%0,%1,%2,%3};"
        : "+f"(c[0]), "+f"(c[1]), "+f"(c[2]), "+f"(c[3])
        : "r"(a[0]), "r"(a[1]), "r"(a[2]), "r"(a[3]), "r"(b[0]), "r"(b[1]));
}

// ---------------- small kernels ----------------
__global__ void init_kernel() { if (threadIdx.x < E_NUM) g_cnt[threadIdx.x] = 0; }

__global__ void __launch_bounds__(256)
router_kernel(const float* __restrict__ x, const float* __restrict__ Wg,
              const float* __restrict__ bg)
{
    const int warp = threadIdx.x >> 5, lane = threadIdx.x & 31;
    const int t = blockIdx.x * 8 + warp;
    const float* xr = x + (size_t)t * D_IN;
    float a0=0,a1=0,a2=0,a3=0;
    for (int d = lane; d < D_IN; d += 32) {
        float xv = xr[d];
        float4 w = ((const float4*)Wg)[d];
        a0 = fmaf(xv,w.x,a0); a1 = fmaf(xv,w.y,a1);
        a2 = fmaf(xv,w.z,a2); a3 = fmaf(xv,w.w,a3);
    }
#pragma unroll
    for (int o = 16; o; o >>= 1) {
        a0 += __shfl_xor_sync(~0u,a0,o); a1 += __shfl_xor_sync(~0u,a1,o);
        a2 += __shfl_xor_sync(~0u,a2,o); a3 += __shfl_xor_sync(~0u,a3,o);
    }
    if (lane == 0) {
        float l[4] = { a0+bg[0], a1+bg[1], a2+bg[2], a3+bg[3] };
        int i0 = 0;
#pragma unroll
        for (int e = 1; e < 4; ++e) if (l[e] > l[i0]) i0 = e;
        int i1 = -1;
#pragma unroll
        for (int e = 0; e < 4; ++e) { if (e==i0) continue; if (i1<0 || l[e]>l[i1]) i1 = e; }
        float r = expf(l[i1]-l[i0]);
        float w0 = 1.f/(1.f+r), w1 = r*w0;
        g_te[2*t]=i0; g_te[2*t+1]=i1; g_tw[2*t]=w0; g_tw[2*t+1]=w1;
        atomicAdd(&g_cnt[i0],1); atomicAdd(&g_cnt[i1],1);
    }
}

__global__ void offsets_kernel() {
    const int tid = threadIdx.x;
    if (tid == 0) {
        int off = 0;
#pragma unroll
        for (int e = 0; e < E_NUM; ++e) {
            g_off[e] = off; off += (g_cnt[e]+127)&~127; g_cur[e] = 0;
        }
        g_off[E_NUM] = off;
    }
    for (int s = tid; s < M_PAD; s += blockDim.x) g_tok[s] = -1;
}

__global__ void scatter_kernel() {
    const int t = blockIdx.x * blockDim.x + threadIdx.x;
    if (t >= T_TOK) return;
#pragma unroll
    for (int k = 0; k < 2; ++k) {
        int e = g_te[2*t+k];
        int p = atomicAdd(&g_cur[e],1);
        int s = g_off[e] + p;
        g_tok[s] = t; g_gw[s] = g_tw[2*t+k]; g_slot_of[2*t+k] = s;
    }
}

// gather x rows into slot order as fp16 (pad rows -> 0)
__global__ void __launch_bounds__(256)
gather_convert_kernel(const float* __restrict__ x)
{
    const int s = blockIdx.x;
    const int tok = g_tok[s];
    __half2* dst = (__half2*)(g_xs + (size_t)s * D_IN);   // 512 half2
    const int i = threadIdx.x;                            // 256 threads, 2 half2 each
    if (tok < 0) {
        dst[2*i]   = __half2half2(__float2half(0.f));
        dst[2*i+1] = __half2half2(__float2half(0.f));
        return;
    }
    float4 v = ((const float4*)(x + (size_t)tok * D_IN))[i];
    dst[2*i]   = __floats2half2_rn(v.x, v.y);
    dst[2*i+1] = __floats2half2_rn(v.z, v.w);
}

// [R][C] -> [C][R] per expert (z), fp16 convert. WHICH selects destination.
template<int WHICH>
__global__ void __launch_bounds__(256)
transpose_convert_kernel(const float* __restrict__ src, int R, int C)
{
    __half* __restrict__ dst = (WHICH == 1) ? g_w1t : g_w2t;
    __shared__ float tile[32][33];
    const size_t so = (size_t)blockIdx.z * R * C;
    const int c0 = blockIdx.x*32, r0 = blockIdx.y*32;
    const int tx = threadIdx.x, ty = threadIdx.y;
#pragma unroll
    for (int i = 0; i < 32; i += 8)
        tile[ty+i][tx] = src[so + (size_t)(r0+ty+i)*C + c0+tx];
    __syncthreads();
#pragma unroll
    for (int i = 0; i < 32; i += 8)
        dst[so + (size_t)(c0+ty+i)*R + r0+tx] = __float2half(tile[tx][ty+i]);
}

// ---------------- fp16 mma.sync GEMM: 128x128x32 CTA tile ----------------
// 8 warps (2m x 4n), warp tile 64x32, m16n8k16 frags via ldmatrix, 4-stage cp.async.
// FIRST=true : A=g_xs (K=1024),  B=g_w1t, epi GELU -> g_h (fp16)
// FIRST=false: A=g_h  (K=4096),  B=g_w2t, epi (acc+b)*gw -> g_eo (fp32)
template<bool FIRST>
__global__ void __launch_bounds__(256, 2)
gemm_mma(const float* __restrict__ bias)
{
    constexpr int K  = FIRST ? D_IN : O_DIM;
    constexpr int KT = K / BK;
    const __half* __restrict__ A  = FIRST ? g_xs  : g_h;
    const __half* __restrict__ Bt = FIRST ? g_w1t : g_w2t;

    extern __shared__ __align__(16) char smem[];
    const uint32_t sb = smem_u32(smem);
    const int tid  = threadIdx.x;
    const int wid  = tid >> 5, lane = tid & 31;
    const int wm   = wid >> 2;           // 0..1
    const int wn   = wid & 3;            // 0..3
    const int n0 = blockIdx.x * BN;
    const int m0 = blockIdx.y * BM;

    int e = 0;
#pragma unroll
    for (int i = 1; i < E_NUM; ++i) if (m0 >= g_off[i]) e = i;

    const __half* Ab = A  + (size_t)m0 * K;
    const __half* Bb = Bt + (size_t)e * O_DIM * K + (size_t)n0 * K;

    // cp.async stage loader: per operand 128 rows x 64B = 512 chunks of 16B
    auto load_stage = [&](int slot, int kblk) {
        const uint32_t sa = sb + slot * STAGE_BYTES;
        const uint32_t sB = sa + AB_BYTES;
        const int k0 = kblk * BK;
#pragma unroll
        for (int q = 0; q < 2; ++q) {
            int f = tid + 256*q;
            int row = f >> 2, c = f & 3;
            CP_ASYNC16(sa + row*(ROW_H*2) + c*16, Ab + (size_t)row*K + k0 + c*8);
            CP_ASYNC16(sB + row*(ROW_H*2) + c*16, Bb + (size_t)row*K + k0 + c*8);
        }
    };

#pragma unroll
    for (int p = 0; p < 3; ++p) {
        if (p < KT) load_stage(p, p);
        CP_COMMIT();
    }

    // ldmatrix lane-address components (byte offsets within a stage)
    //  A (mt): row = wm*64 + mt*16 + (lane&15), 16B-col = lane>>4
    const int a_row = wm*64 + (lane & 15);
    const uint32_t a_off0 = (uint32_t)a_row * (ROW_H*2) + ((lane >> 4) << 4);
    //  B (pair): row = wn*32 + pair*16 + ((lane>>4)<<3) + (lane&7), 16B-col = (lane>>3)&1
    const int b_row = wn*32 + ((lane >> 4) << 3) + (lane & 7);
    const uint32_t b_off0 = (uint32_t)b_row * (ROW_H*2) + (((lane >> 3) & 1) << 4);

    float c[4][4][4];
#pragma unroll
    for (int mt = 0; mt < 4; ++mt)
#pragma unroll
        for (int nt = 0; nt < 4; ++nt)
#pragma unroll
            for (int i = 0; i < 4; ++i) c[mt][nt][i] = 0.f;

    for (int it = 0; it < KT; ++it) {
        CP_WAIT2();
        __syncthreads();
        if (it + 3 < KT) load_stage((it + 3) & (NSTAGE-1), it + 3);
        CP_COMMIT();

        const uint32_t sa = sb + (it & (NSTAGE-1)) * STAGE_BYTES;
        const uint32_t sB = sa + AB_BYTES;

#pragma unroll
        for (int ks = 0; ks < 2; ++ks) {           // 2 x k16 per BK=32
            const uint32_t kadd = ks * 32;          // 16 halfs = 32B
            uint32_t a[4][4];
#pragma unroll
            for (int mt = 0; mt < 4; ++mt)
                LDSM_X4(a[mt][0], a[mt][1], a[mt][2], a[mt][3],
                        sa + a_off0 + mt*16*(ROW_H*2) + kadd);
            uint32_t b[4][2];
#pragma unroll
            for (int pr = 0; pr < 2; ++pr) {
                uint32_t r0, r1, r2, r3;
                LDSM_X4(r0, r1, r2, r3, sB + b_off0 + pr*16*(ROW_H*2) + kadd);
                b[2*pr][0] = r0; b[2*pr][1] = r1;
                b[2*pr+1][0] = r2; b[2*pr+1][1] = r3;
            }
#pragma unroll
            for (int mt = 0; mt < 4; ++mt)
#pragma unroll
                for (int nt = 0; nt < 4; ++nt)
                    mma16n8k16(c[mt][nt], a[mt], b[nt]);
        }
    }

    // ---------------- epilogue ----------------
    const int lq = lane >> 2, lr = lane & 3;
#pragma unroll
    for (int mt = 0; mt < 4; ++mt) {
        const int r0 = m0 + wm*64 + mt*16 + lq;
        const int r1 = r0 + 8;
        const float gw0 = FIRST ? 1.f : g_gw[r0];
        const float gw1 = FIRST ? 1.f : g_gw[r1];
#pragma unroll
        for (int nt = 0; nt < 4; ++nt) {
            const int col = n0 + wn*32 + nt*8 + 2*lr;
            const float b0 = bias[e*O_DIM + col];
            const float b1 = bias[e*O_DIM + col + 1];
            float v00 = c[mt][nt][0] + b0, v01 = c[mt][nt][1] + b1;
            float v10 = c[mt][nt][2] + b0, v11 = c[mt][nt][3] + b1;
            if (FIRST) {
                v00 = 0.5f*v00*(1.f+erff(v00*0.70710678118654752f));
                v01 = 0.5f*v01*(1.f+erff(v01*0.70710678118654752f));
                v10 = 0.5f*v10*(1.f+erff(v10*0.70710678118654752f));
                v11 = 0.5f*v11*(1.f+erff(v11*0.70710678118654752f));
                *(__half2*)(g_h + (size_t)r0*O_DIM + col) = __floats2half2_rn(v00, v01);
                *(__half2*)(g_h + (size_t)r1*O_DIM + col) = __floats2half2_rn(v10, v11);
            } else {
                *(float2*)(g_eo + (size_t)r0*O_DIM + col) = make_float2(v00*gw0, v01*gw0);
                *(float2*)(g_eo + (size_t)r1*O_DIM + col) = make_float2(v10*gw1, v11*gw1);
            }
        }
    }
}

// ---------------- combine two expert outputs + LayerNorm ----------------
__global__ void __launch_bounds__(256)
combine_ln_kernel(const float* __restrict__ ln_w, const float* __restrict__ ln_b,
                  const float* __restrict__ gate_scale, float* __restrict__ out)
{
    __shared__ __align__(16) float buf[O_DIM];
    __shared__ float s_red[32];
    __shared__ float s_mean, s_rstd;

    const int t = blockIdx.x, tid = threadIdx.x;
    const int sA = g_slot_of[2*t], sB = g_slot_of[2*t+1];
    const float4* ea = (const float4*)(g_eo + (size_t)sA * O_DIM);
    const float4* eb = (const float4*)(g_eo + (size_t)sB * O_DIM);
    const float gs = gate_scale[0];

    float sum = 0.f;
    for (int i = tid; i < O_DIM/4; i += 256) {
        float4 a = ea[i], b = eb[i];
        float4 v = make_float4(gs*(a.x+b.x), gs*(a.y+b.y), gs*(a.z+b.z), gs*(a.w+b.w));
        ((float4*)buf)[i] = v;
        sum += v.x + v.y + v.z + v.w;
    }
#pragma unroll
    for (int o = 16; o; o >>= 1) sum += __shfl_xor_sync(~0u, sum, o);
    if ((tid & 31) == 0) s_red[tid >> 5] = sum;
    __syncthreads();
    if (tid < 32) {
        float v = (tid < 8) ? s_red[tid] : 0.f;
#pragma unroll
        for (int o = 4; o; o >>= 1) v += __shfl_xor_sync(~0u, v, o);
        if (tid == 0) s_mean = v * (1.f / O_DIM);
    }
    __syncthreads();
    const float mu = s_mean;

    float ssq = 0.f;
    for (int i = tid; i < O_DIM; i += 256) { float d = buf[i]-mu; ssq += d*d; }
#pragma unroll
    for (int o = 16; o; o >>= 1) ssq += __shfl_xor_sync(~0u, ssq, o);
    __syncthreads();
    if ((tid & 31) == 0) s_red[tid >> 5] = ssq;
    __syncthreads();
    if (tid < 32) {
        float v = (tid < 8) ? s_red[tid] : 0.f;
#pragma unroll
        for (int o = 4; o; o >>= 1) v += __shfl_xor_sync(~0u, v, o);
        if (tid == 0) s_rstd = rsqrtf(v * (1.f / O_DIM) + 1e-5f);
    }
    __syncthreads();
    const float rstd = s_rstd;

    float4* op = (float4*)(out + (size_t)t * O_DIM);
    const float4* lw = (const float4*)ln_w;
    const float4* lb = (const float4*)ln_b;
    for (int i = tid; i < O_DIM/4; i += 256) {
        float4 v = ((float4*)buf)[i], w = lw[i], b = lb[i];
        op[i] = make_float4((v.x-mu)*rstd*w.x+b.x, (v.y-mu)*rstd*w.y+b.y,
                            (v.z-mu)*rstd*w.z+b.z, (v.w-mu)*rstd*w.w+b.w);
    }
}

// ---------------- launch ----------------
extern "C" void kernel_launch(void* const* d_in, const int* in_sizes, int n_in,
                              void* d_out, int out_size)
{
    (void)in_sizes; (void)n_in; (void)out_size;
    const float* x  = (const float*)d_in[0];
    const float* Wg = (const float*)d_in[1];
    const float* bg = (const float*)d_in[2];
    const float* W1 = (const float*)d_in[3];
    const float* b1 = (const float*)d_in[4];
    const float* W2 = (const float*)d_in[5];
    const float* b2 = (const float*)d_in[6];
    const float* lw = (const float*)d_in[7];
    const float* lb = (const float*)d_in[8];
    const float* gs = (const float*)d_in[9];
    float* out = (float*)d_out;

    cudaFuncSetAttribute(gemm_mma<true>,  cudaFuncAttributeMaxDynamicSharedMemorySize, SMEM_TOTAL);
    cudaFuncSetAttribute(gemm_mma<false>, cudaFuncAttributeMaxDynamicSharedMemorySize, SMEM_TOTAL);

    init_kernel<<<1, 32>>>();
    router_kernel<<<T_TOK/8, 256>>>(x, Wg, bg);
    offsets_kernel<<<1, 256>>>();
    scatter_kernel<<<T_TOK/256, 256>>>();
    gather_convert_kernel<<<M_PAD, 256>>>(x);
    transpose_convert_kernel<1><<<dim3(O_DIM/32, D_IN/32, E_NUM), dim3(32,8)>>>(W1, D_IN, O_DIM);
    transpose_convert_kernel<2><<<dim3(O_DIM/32, O_DIM/32, E_NUM), dim3(32,8)>>>(W2, O_DIM, O_DIM);

    gemm_mma<true ><<<dim3(NT, MT), 256, SMEM_TOTAL>>>(b1);
    gemm_mma<false><<<dim3(NT, MT), 256, SMEM_TOTAL>>>(b2);

    combine_ln_kernel<<<T_TOK, 256>>>(lw, lb, gs, out);
}